// round 11
// baseline (speedup 1.0000x reference)
#include <cuda_runtime.h>
#include <math.h>

#define BB 2
#define LL 225
#define DD 256
#define HH 4
#define HD 64
#define BH 8
#define NROW 450
#define LP 240

// ---------------- scratch ----------------------------------------------------
__device__ __align__(16) float g_q[BH*LL*HD];
__device__ __align__(16) float g_k[BH*LL*HD];
__device__ __align__(16) float g_v[BH*LL*HD];
__device__ __align__(16) float g_S[BH*LL*LP + 16];
__device__ __align__(16) float g_A0[BH*LL*LP + 16];
__device__ __align__(16) float g_A1[BH*LL*LP + 16];
__device__ __align__(16) float g_A2[BH*LL*LP + 16];
__device__ __align__(16) float g_Ah[BH*LL*LP + 16];
__device__ __align__(16) float g_T[BH*LL*LP + 16];
__device__ __align__(16) float g_P[BH*LL*LP + 16];
__device__ __align__(16) float g_O[NROW*DD];
__device__ float g_deg[BH*LP];
__device__ unsigned g_gbar;    // cumulative; never reset (replay-safe)

// ---------------- helpers -----------------------------------------------------
__device__ __forceinline__ float4 ld4(const float* p) { return *(const float4*)p; }
__device__ __forceinline__ float4 f4z() { return make_float4(0.f, 0.f, 0.f, 0.f); }

__device__ __forceinline__ unsigned long long pk2(float lo, float hi) {
    unsigned long long r;
    asm("mov.b64 %0,{%1,%2};" : "=l"(r) : "f"(lo), "f"(hi));
    return r;
}
__device__ __forceinline__ void fma2(unsigned long long& d,
                                     unsigned long long a, unsigned long long b) {
    asm("fma.rn.f32x2 %0,%1,%2,%0;" : "+l"(d) : "l"(a), "l"(b));
}
__device__ __forceinline__ float2 up2(unsigned long long v) {
    float2 f;
    asm("mov.b64 {%0,%1},%2;" : "=f"(f.x), "=f"(f.y) : "l"(v));
    return f;
}

// grid barrier: cumulative counter, plain spin (1 thread/block polls L2)
__device__ __forceinline__ void grid_sync(unsigned nb) {
    __syncthreads();
    if (threadIdx.x == 0 && threadIdx.y == 0) {
        __threadfence();
        unsigned old = atomicAdd(&g_gbar, 1u);
        unsigned target = old - (old % nb) + nb;
        while (*((volatile unsigned*)&g_gbar) < target) {}
        __threadfence();
    }
    __syncthreads();
}

// C[4][4] += A(.. x16, stride AST) * B(16 x .., stride BST), packed f32x2
template<int AST, int BST>
__device__ __forceinline__ void inner16(const float* As, const float* Bs,
                                        int ty4, int tx4, unsigned long long acc[4][2]) {
#pragma unroll
    for (int kk = 0; kk < 16; kk++) {
        float4 bv = *(const float4*)(Bs + kk*BST + tx4);
        unsigned long long b01 = pk2(bv.x, bv.y);
        unsigned long long b23 = pk2(bv.z, bv.w);
#pragma unroll
        for (int r = 0; r < 4; r++) {
            float ar = As[(ty4 + r)*AST + kk];
            unsigned long long aa = pk2(ar, ar);
            fma2(acc[r][0], aa, b01);
            fma2(acc[r][1], aa, b23);
        }
    }
}

// ---------------- phase 0: qkv (64 rows x 64 cols, K=256), 96 tiles -------------
__device__ __forceinline__ void qkv_tile(int t, const float* __restrict__ x,
                                         const float* __restrict__ Wq,
                                         const float* __restrict__ Wk,
                                         const float* __restrict__ Wv,
                                         float* sAf, float* sBf,
                                         int tid, int tx, int ty) {
    float (*Xs)[20] = (float(*)[20])sAf;
    float (*Ws)[68] = (float(*)[68])sBf;
    int mt = t & 7, ct = t >> 3;          // 8 m-tiles x 12 c-tiles
    int m0 = mt*64;
    const float* W = (ct < 4) ? Wq : (ct < 8) ? Wk : Wv;
    int cw0 = (ct & 3) * 64;
    unsigned long long acc[4][2] = {};
    for (int k0 = 0; k0 < 256; k0 += 16) {
        { int ii = tid >> 2, f = tid & 3;
          int m = m0 + ii;
          float4 v = (m < NROW) ? ld4(x + m*256 + k0 + 4*f) : f4z();
          *(float4*)&Xs[ii][4*f] = v; }
        { int ll = tid >> 2, f = tid & 3;
          float4 w = ld4(W + (cw0 + ll)*256 + k0 + 4*f);
          Ws[4*f+0][ll] = w.x; Ws[4*f+1][ll] = w.y;
          Ws[4*f+2][ll] = w.z; Ws[4*f+3][ll] = w.w; }
        __syncthreads();
        inner16<20, 68>(&Xs[0][0], &Ws[0][0], ty*4, tx*4, acc);
        __syncthreads();
    }
    int which = ct >> 2, hb = ct & 3;
    float* dst = (which == 0) ? g_q : (which == 1) ? g_k : g_v;
#pragma unroll
    for (int r = 0; r < 4; r++) {
        int m = m0 + ty*4 + r;
        if (m < NROW) {
            int b = (m >= LL) ? 1 : 0;
            int l = m - b*LL;
            float2 lo = up2(acc[r][0]), hi = up2(acc[r][1]);
            *(float4*)(dst + ((b*HH + hb)*LL + l)*HD + tx*4) =
                make_float4(lo.x, lo.y, hi.x, hi.y);
        }
    }
}

// ---------------- phase 1: S = q k^T (64x64, K=64), 128 tiles -------------------
__device__ __forceinline__ void s_tile(int t, float* sAf, float* sBf,
                                       int tid, int tx, int ty) {
    float (*Qs)[20] = (float(*)[20])sAf;
    float (*Ks)[68] = (float(*)[68])sBf;
    int bh = t >> 4, rr = t & 15;
    int i0 = (rr >> 2)*64, j0 = (rr & 3)*64;
    const float* qb = g_q + bh*LL*HD;
    const float* kb = g_k + bh*LL*HD;
    unsigned long long acc[4][2] = {};
#pragma unroll
    for (int d0 = 0; d0 < 64; d0 += 16) {
        { int ii = tid >> 2, f = tid & 3;
          int i = i0 + ii;
          float4 v = (i < LL) ? ld4(qb + i*HD + d0 + 4*f) : f4z();
          *(float4*)&Qs[ii][4*f] = v; }
        { int ll = tid >> 2, f = tid & 3;
          int j = j0 + ll;
          float4 v = (j < LL) ? ld4(kb + j*HD + d0 + 4*f) : f4z();
          Ks[4*f+0][ll] = v.x; Ks[4*f+1][ll] = v.y;
          Ks[4*f+2][ll] = v.z; Ks[4*f+3][ll] = v.w; }
        __syncthreads();
        inner16<20, 68>(&Qs[0][0], &Ks[0][0], ty*4, tx*4, acc);
        __syncthreads();
    }
    float* Sb = g_S + (size_t)bh*LL*LP;
    int jc = j0 + tx*4;
    if (jc < LP) {
#pragma unroll
        for (int r = 0; r < 4; r++) {
            int i = i0 + ty*4 + r;
            if (i < LL) {
                float2 lo = up2(acc[r][0]), hi = up2(acc[r][1]);
                *(float4*)(Sb + i*LP + jc) = make_float4(lo.x, lo.y, hi.x, hi.y);
            }
        }
    }
}

// ---------------- phase 2: adjacency 64x64 symmetric pairs, j-split x3 ----------
// 240 tiles: t = js*80 + bh*10 + p
__device__ __forceinline__ void a_tile(int t, float* sAf, float* sBf, float* sXf,
                                       int tid, int tx, int ty) {
    float (*Si)[16][68] = (float(*)[16][68])sAf;
    float (*Sk)[16][68] = (float(*)[16][68])sBf;
    float* scol = sXf;
    int js = t / 80, rem0 = t % 80;
    int bh = rem0 / 10, p = rem0 % 10;
    int jbase = js * 80;
    const int NC = 5;
    int ti = 0, rem = p;
    while (rem >= 4 - ti) { rem -= 4 - ti; ti++; }
    int tk = ti + rem;
    int i0 = ti*64, k0 = tk*64;
    const float* Sb = g_S + (size_t)bh*LL*LP;
    const float THR = 6.4f;   // == 0.1f*64 exactly
    if (tid < 64) scol[tid] = 0.f;

    bool isI = tid < 128;
    int lr = (tid & 127) >> 1;
    int lf = (tid & 1) * 8;
    int lrow = (isI ? i0 : k0) + lr;
    float4 r0, r1;

    auto loadc = [&](int c) {
        int jb = jbase + c*16 + lf;
        if (lrow < LL) {
            r0 = ld4(Sb + lrow*LP + jb);
            r1 = ld4(Sb + lrow*LP + jb + 4);
        } else { r0 = f4z(); r1 = f4z(); }
    };
    auto storec = [&](int st) {
        float (*Ds)[68] = isI ? Si[st] : Sk[st];
        Ds[lf+0][lr] = r0.x; Ds[lf+1][lr] = r0.y;
        Ds[lf+2][lr] = r0.z; Ds[lf+3][lr] = r0.w;
        Ds[lf+4][lr] = r1.x; Ds[lf+5][lr] = r1.y;
        Ds[lf+6][lr] = r1.z; Ds[lf+7][lr] = r1.w;
    };

    float a[4][4] = {};
    loadc(0); storec(0); __syncthreads();
    for (int c = 0; c < NC; c++) {
        int st = c & 1;
        if (c + 1 < NC) loadc(c + 1);
#pragma unroll
        for (int kk = 0; kk < 16; kk++) {
            float4 a4 = *(const float4*)&Si[st][kk][ty*4];
            float4 b4 = *(const float4*)&Sk[st][kk][tx*4];
            float tt;
            tt = a4.x*b4.x; if (tt > THR) a[0][0] += tt;
            tt = a4.x*b4.y; if (tt > THR) a[0][1] += tt;
            tt = a4.x*b4.z; if (tt > THR) a[0][2] += tt;
            tt = a4.x*b4.w; if (tt > THR) a[0][3] += tt;
            tt = a4.y*b4.x; if (tt > THR) a[1][0] += tt;
            tt = a4.y*b4.y; if (tt > THR) a[1][1] += tt;
            tt = a4.y*b4.z; if (tt > THR) a[1][2] += tt;
            tt = a4.y*b4.w; if (tt > THR) a[1][3] += tt;
            tt = a4.z*b4.x; if (tt > THR) a[2][0] += tt;
            tt = a4.z*b4.y; if (tt > THR) a[2][1] += tt;
            tt = a4.z*b4.z; if (tt > THR) a[2][2] += tt;
            tt = a4.z*b4.w; if (tt > THR) a[2][3] += tt;
            tt = a4.w*b4.x; if (tt > THR) a[3][0] += tt;
            tt = a4.w*b4.y; if (tt > THR) a[3][1] += tt;
            tt = a4.w*b4.z; if (tt > THR) a[3][2] += tt;
            tt = a4.w*b4.w; if (tt > THR) a[3][3] += tt;
        }
        if (c + 1 < NC) storec(st ^ 1);
        __syncthreads();
    }

    const float sc = 1.f / (64.f * 225.f);
    int ig0 = i0 + ty*4, kg0 = k0 + tx*4;
    float av[4][4];
#pragma unroll
    for (int r = 0; r < 4; r++)
#pragma unroll
        for (int c = 0; c < 4; c++) {
            float v = a[r][c] * sc;
            av[r][c] = (ig0 + r == kg0 + c) ? 0.f : v;
        }
    float* Ab = ((js == 0) ? g_A0 : (js == 1) ? g_A1 : g_A2) + (size_t)bh*LL*LP;
    if (kg0 < LP) {
#pragma unroll
        for (int r = 0; r < 4; r++) {
            int ig = ig0 + r;
            if (ig < LL)
                *(float4*)(Ab + ig*LP + kg0) =
                    make_float4(av[r][0], av[r][1], av[r][2], av[r][3]);
        }
    }
    if (ti != tk) {
#pragma unroll
        for (int c = 0; c < 4; c++) {
            int kg = kg0 + c;
            if (kg < LL)
                *(float4*)(Ab + kg*LP + ig0) =
                    make_float4(av[0][c], av[1][c], av[2][c], av[3][c]);
        }
    }
#pragma unroll
    for (int r = 0; r < 4; r++) {
        float rs = (av[r][0] + av[r][1]) + (av[r][2] + av[r][3]);
#pragma unroll
        for (int off = 8; off > 0; off >>= 1)
            rs += __shfl_xor_sync(0xffffffffu, rs, off);
        int ig = ig0 + r;
        if (tx == 0 && ig < LL) atomicAdd(&g_deg[bh*LP + ig], rs);
    }
    if (ti != tk) {
#pragma unroll
        for (int c = 0; c < 4; c++) {
            float cs = (av[0][c] + av[1][c]) + (av[2][c] + av[3][c]);
            atomicAdd(&scol[tx*4 + c], cs);
        }
        __syncthreads();
        if (tid < 64) {
            int kg = k0 + tid;
            if (kg < LL) atomicAdd(&g_deg[bh*LP + kg], scol[tid]);
        }
    }
    __syncthreads();   // scol reuse safety (single tile per phase anyway)
}

// ---------------- phase 3: Ah = (A0+A1+A2 + I)*dis_i*dis_k/sqrt(8), 232 tiles ---
__device__ __forceinline__ void ahat_tile(int t, float* sXf, int tid) {
    float* sdis = sXf;
    int rg = t % 29, bh = t / 29;
    if (tid < LP) sdis[tid] = rsqrtf(fmaxf(1.f + g_deg[bh*LP + tid], 1e-6f));
    __syncthreads();
    const float SC = 0.35355339059327373f;  // 1/sqrt(8)
    size_t off = (size_t)bh*LL*LP;
    const float* A0 = g_A0 + off;
    const float* A1 = g_A1 + off;
    const float* A2 = g_A2 + off;
    float* Ah = g_Ah + off;
#pragma unroll
    for (int s = 0; s < 2; s++) {
        int idx = tid + s*256;
        if (idx < 8*60) {
            int r = idx / 60, c4 = (idx % 60) * 4;
            int i = rg*8 + r;
            if (i < LL) {
                float4 a0 = ld4(A0 + i*LP + c4);
                float4 a1 = ld4(A1 + i*LP + c4);
                float4 a2 = ld4(A2 + i*LP + c4);
                float di = sdis[i] * SC;
                float4 dk = *(const float4*)&sdis[c4];
                float4 o;
                o.x = (a0.x + a1.x + a2.x + ((i == c4 + 0) ? 1.f : 0.f)) * di * dk.x;
                o.y = (a0.y + a1.y + a2.y + ((i == c4 + 1) ? 1.f : 0.f)) * di * dk.y;
                o.z = (a0.z + a1.z + a2.z + ((i == c4 + 2) ? 1.f : 0.f)) * di * dk.z;
                o.w = (a0.w + a1.w + a2.w + ((i == c4 + 3) ? 1.f : 0.f)) * di * dk.w;
                *(float4*)(Ah + i*LP + c4) = o;
            }
        }
    }
    __syncthreads();
}

// ---------------- phases 4/5: 225^3 GEMM, 64x64 tile, k-split x2, 256 tiles -----
// MODE 0: partials of Ah @ S -> T(ks0)/P(ks1)
// MODE 1: partials of (T+P) @ Ah -> A0(ks0)/A1(ks1)
__device__ __forceinline__ void gemm_tile_f(int MODE, int t,
                                            float* sAf, float* sBf,
                                            int tid, int tx, int ty) {
    float (*As)[16][68] = (float(*)[16][68])sAf;
    float (*Bs)[16][68] = (float(*)[16][68])sBf;
    int bh = t >> 5, r5 = t & 31;
    int ks = r5 >> 4, rr = r5 & 15;
    int kbase = ks ? 128 : 0;
    int NC = ks ? 7 : 8;
    int i0 = (rr >> 2)*64, j0 = (rr & 3)*64;
    size_t off = (size_t)bh*LL*LP;
    const float* A1p = ((MODE == 0) ? g_Ah : g_T) + off;
    const float* A2p = g_P + off;
    const float* B   = ((MODE == 0) ? g_S : g_Ah) + off;
    float* C = (MODE == 0) ? ((ks ? g_P : g_T) + off)
                           : ((ks ? g_A1 : g_A0) + off);

    int alr = tid >> 2;
    int alf = (tid & 3) * 4;
    int arow = i0 + alr;
    int bkk = tid >> 4, bj4 = (tid & 15) * 4;
    int bj = j0 + bj4;
    float4 aReg = f4z(), bReg = f4z();

    auto loadc = [&](int c) {
        int kabs = kbase + c*16;
        if (arow < LL) {
            aReg = ld4(A1p + arow*LP + kabs + alf);
            if (MODE == 1) {
                float4 w = ld4(A2p + arow*LP + kabs + alf);
                aReg.x += w.x; aReg.y += w.y; aReg.z += w.z; aReg.w += w.w;
            }
        } else aReg = f4z();
        int k = kabs + bkk;
        bReg = (k < LL && bj < LP) ? ld4(B + k*LP + bj) : f4z();
    };
    auto storec = [&](int st) {
        As[st][alf+0][alr] = aReg.x; As[st][alf+1][alr] = aReg.y;
        As[st][alf+2][alr] = aReg.z; As[st][alf+3][alr] = aReg.w;
        *(float4*)&Bs[st][bkk][bj4] = bReg;
    };

    unsigned long long acc[4][2] = {};
    loadc(0); storec(0); __syncthreads();
    for (int c = 0; c < NC; c++) {
        int st = c & 1;
        if (c + 1 < NC) loadc(c + 1);
#pragma unroll
        for (int kk = 0; kk < 16; kk++) {
            float4 a4 = *(const float4*)&As[st][kk][ty*4];
            float4 b4 = *(const float4*)&Bs[st][kk][tx*4];
            unsigned long long b01 = pk2(b4.x, b4.y);
            unsigned long long b23 = pk2(b4.z, b4.w);
            unsigned long long aa;
            aa = pk2(a4.x, a4.x); fma2(acc[0][0], aa, b01); fma2(acc[0][1], aa, b23);
            aa = pk2(a4.y, a4.y); fma2(acc[1][0], aa, b01); fma2(acc[1][1], aa, b23);
            aa = pk2(a4.z, a4.z); fma2(acc[2][0], aa, b01); fma2(acc[2][1], aa, b23);
            aa = pk2(a4.w, a4.w); fma2(acc[3][0], aa, b01); fma2(acc[3][1], aa, b23);
        }
        if (c + 1 < NC) storec(st ^ 1);
        __syncthreads();
    }

    int jc = j0 + tx*4;
    if (jc < LP) {
#pragma unroll
        for (int r = 0; r < 4; r++) {
            int i = i0 + ty*4 + r;
            if (i < LL) {
                float2 lo = up2(acc[r][0]), hi = up2(acc[r][1]);
                *(float4*)(C + i*LP + jc) = make_float4(lo.x, lo.y, hi.x, hi.y);
            }
        }
    }
}

// ---------------- phase 6: fused softmax + O = attn @ v (A0+A1 partials), 120 ---
__device__ __forceinline__ void av_tile(int t, float* sAf, float* sBf, float* sXf,
                                        int tid, int tx, int ty) {
    float2 (*PsD)[18] = (float2(*)[18])sAf;
    float  (*Vs)[68]  = (float(*)[68])sBf;
    float* smx = sXf;
    float* sinv = sXf + 16;
    int bh = t / 15, i0 = (t % 15) * 16;
    const float* P0 = g_A0 + (size_t)bh*LL*LP;
    const float* P1 = g_A1 + (size_t)bh*LL*LP;
    const float* Vb = g_v + bh*LL*HD;
    {
        int w = tid >> 5, lane = tid & 31;
#pragma unroll
        for (int rr = 0; rr < 2; rr++) {
            int row = w*2 + rr;
            int i = i0 + row;
            if (i < LL) {
                const float* Pr0 = P0 + i*LP;
                const float* Pr1 = P1 + i*LP;
                float vb[8];
                float m = -1e30f;
#pragma unroll
                for (int e = 0; e < 8; e++) {
                    int j = lane + 32*e;
                    float v = (j < LL) ? (Pr0[j] + Pr1[j]) : -1e30f;
                    vb[e] = v;
                    m = fmaxf(m, v);
                }
#pragma unroll
                for (int off = 16; off > 0; off >>= 1)
                    m = fmaxf(m, __shfl_xor_sync(0xffffffffu, m, off));
                float s = 0.f;
#pragma unroll
                for (int e = 0; e < 8; e++) s += __expf(vb[e] - m);
#pragma unroll
                for (int off = 16; off > 0; off >>= 1)
                    s += __shfl_xor_sync(0xffffffffu, s, off);
                if (lane == 0) { smx[row] = m; sinv[row] = 1.f / s; }
            }
        }
    }
    __syncthreads();
    unsigned long long acc[2] = {};
    for (int k0 = 0; k0 < LP; k0 += 16) {
        if (tid < 64) {
            int row = tid >> 2, f = (tid & 3)*4;
            int i = i0 + row;
            float4 v;
            if (i < LL) {
                float4 v0 = ld4(P0 + i*LP + k0 + f);
                float4 v1 = ld4(P1 + i*LP + k0 + f);
                float m = smx[row], inv = sinv[row];
                int kb = k0 + f;
                v.x = (kb + 0 < LL) ? __expf(v0.x + v1.x - m)*inv : 0.f;
                v.y = (kb + 1 < LL) ? __expf(v0.y + v1.y - m)*inv : 0.f;
                v.z = (kb + 2 < LL) ? __expf(v0.z + v1.z - m)*inv : 0.f;
                v.w = (kb + 3 < LL) ? __expf(v0.w + v1.w - m)*inv : 0.f;
            } else v = f4z();
            PsD[f+0][row] = make_float2(v.x, v.x);
            PsD[f+1][row] = make_float2(v.y, v.y);
            PsD[f+2][row] = make_float2(v.z, v.z);
            PsD[f+3][row] = make_float2(v.w, v.w);
        }
        { int kk = tid >> 4, d4 = (tid & 15)*4;
          int k = k0 + kk;
          float4 v = (k < LL) ? ld4(Vb + k*HD + d4) : f4z();
          *(float4*)&Vs[kk][d4] = v; }
        __syncthreads();
#pragma unroll
        for (int kk = 0; kk < 16; kk++) {
            unsigned long long a = *(const unsigned long long*)&PsD[kk][ty];
            ulonglong2 b = *(const ulonglong2*)&Vs[kk][tx*4];
            fma2(acc[0], a, b.x);
            fma2(acc[1], a, b.y);
        }
        __syncthreads();
    }
    int b = bh >> 2, h = bh & 3;
    int i = i0 + ty;
    if (i < LL) {
        float2 lo = up2(acc[0]), hi = up2(acc[1]);
        *(float4*)(g_O + (b*LL + i)*DD + h*HD + tx*4) =
            make_float4(lo.x, lo.y, hi.x, hi.y);
    }
}

// ---------------- phase 7: out = O @ Wo^T, 60 tiles ------------------------------
__device__ __forceinline__ void out_tile(int t, const float* __restrict__ Wo,
                                         float* __restrict__ out,
                                         float* sAf, float* sBf,
                                         int tid, int tx, int ty) {
    float (*Os)[20] = (float(*)[20])sAf;
    float (*Ws)[68] = (float(*)[68])sBf;
    int m0 = (t >> 2)*32, c0 = (t & 3)*64;
    unsigned long long acc[2][2] = {};
    for (int k0 = 0; k0 < 256; k0 += 16) {
        if (tid < 128) {
            int ii = tid >> 2, f = tid & 3;
            int m = m0 + ii;
            float4 v = (m < NROW) ? ld4(g_O + m*256 + k0 + 4*f) : f4z();
            *(float4*)&Os[ii][4*f] = v;
        } else {
#pragma unroll
            for (int s2 = 0; s2 < 2; s2++) {
                int idx = (tid - 128) + 128*s2;
                int ll = idx >> 2, f = idx & 3;
                float4 w = ld4(Wo + (c0 + ll)*256 + k0 + 4*f);
                Ws[4*f+0][ll] = w.x; Ws[4*f+1][ll] = w.y;
                Ws[4*f+2][ll] = w.z; Ws[4*f+3][ll] = w.w;
            }
        }
        __syncthreads();
#pragma unroll
        for (int kk = 0; kk < 16; kk++) {
            float4 bv = *(const float4*)&Ws[kk][tx*4];
            unsigned long long b01 = pk2(bv.x, bv.y);
            unsigned long long b23 = pk2(bv.z, bv.w);
#pragma unroll
            for (int r = 0; r < 2; r++) {
                float ar = Os[ty*2 + r][kk];
                unsigned long long aa = pk2(ar, ar);
                fma2(acc[r][0], aa, b01);
                fma2(acc[r][1], aa, b23);
            }
        }
        __syncthreads();
    }
#pragma unroll
    for (int r = 0; r < 2; r++) {
        int m = m0 + ty*2 + r;
        if (m < NROW) {
            float2 lo = up2(acc[r][0]), hi = up2(acc[r][1]);
            *(float4*)(out + m*256 + c0 + tx*4) =
                make_float4(lo.x, lo.y, hi.x, hi.y);
        }
    }
}

// ---------------- fused persistent kernel ----------------------------------------
__global__ void __launch_bounds__(256, 2)
fused_kernel(const float* __restrict__ x, const float* __restrict__ Wq,
             const float* __restrict__ Wk, const float* __restrict__ Wv,
             const float* __restrict__ Wo, float* __restrict__ out, int nb) {
    __shared__ __align__(16) float sA[2176];
    __shared__ __align__(16) float sB[2176];
    __shared__ __align__(16) float sX[256];
    int tx = threadIdx.x, ty = threadIdx.y;
    int tid = ty*16 + tx;

    for (int i = blockIdx.x*256 + tid; i < BH*LP; i += nb*256) g_deg[i] = 0.f;
    for (int t = blockIdx.x; t < 96; t += nb) qkv_tile(t, x, Wq, Wk, Wv, sA, sB, tid, tx, ty);
    grid_sync(nb);
    for (int t = blockIdx.x; t < 128; t += nb) s_tile(t, sA, sB, tid, tx, ty);
    grid_sync(nb);
    for (int t = blockIdx.x; t < 240; t += nb) a_tile(t, sA, sB, sX, tid, tx, ty);
    grid_sync(nb);
    for (int t = blockIdx.x; t < 232; t += nb) ahat_tile(t, sX, tid);
    grid_sync(nb);
    for (int t = blockIdx.x; t < 256; t += nb) gemm_tile_f(0, t, sA, sB, tid, tx, ty);
    grid_sync(nb);
    for (int t = blockIdx.x; t < 256; t += nb) gemm_tile_f(1, t, sA, sB, tid, tx, ty);
    grid_sync(nb);
    for (int t = blockIdx.x; t < 120; t += nb) av_tile(t, sA, sB, sX, tid, tx, ty);
    grid_sync(nb);
    for (int t = blockIdx.x; t < 60; t += nb) out_tile(t, Wo, out, sA, sB, tid, tx, ty);
}

// ---------------- launcher --------------------------------------------------------
extern "C" void kernel_launch(void* const* d_in, const int* in_sizes, int n_in,
                              void* d_out, int out_size) {
    const float* x  = (const float*)d_in[0];
    const float* Wq = (const float*)d_in[1];
    const float* Wk = (const float*)d_in[2];
    const float* Wv = (const float*)d_in[3];
    const float* Wo = (const float*)d_in[4];
    float* out = (float*)d_out;

    int dev = 0;
    cudaGetDevice(&dev);
    int nsm = 0;
    cudaDeviceGetAttribute(&nsm, cudaDevAttrMultiProcessorCount, dev);
    if (nsm <= 0) nsm = 148;
    int per = 0;
    cudaOccupancyMaxActiveBlocksPerMultiprocessor(&per, fused_kernel, 256, 0);
    if (per < 1) per = 1;
    long nbl = (long)per * (long)nsm;
    if (nbl > 296) nbl = 296;
    int nb = (int)nbl;

    fused_kernel<<<nb, dim3(16, 16)>>>(x, Wq, Wk, Wv, Wo, out, nb);
}

// round 13
// speedup vs baseline: 1.1195x; 1.1195x over previous
#include <cuda_runtime.h>
#include <math.h>

#define BB 2
#define LL 225
#define DD 256
#define HH 4
#define HD 64
#define BH 8
#define NROW 450
#define LP 240

// ---------------- scratch ----------------------------------------------------
__device__ __align__(16) float g_q[BH*LL*HD];
__device__ __align__(16) float g_k[BH*LL*HD];
__device__ __align__(16) float g_v[BH*LL*HD];
__device__ __align__(16) float g_S[BH*LL*LP + 16];
__device__ __align__(16) float g_A0[BH*LL*LP + 16];
__device__ __align__(16) float g_A1[BH*LL*LP + 16];
__device__ __align__(16) float g_A2[BH*LL*LP + 16];
__device__ __align__(16) float g_A3[BH*LL*LP + 16];
__device__ __align__(16) float g_A4[BH*LL*LP + 16];
__device__ __align__(16) float g_Ah[BH*LL*LP + 16];
__device__ __align__(16) float g_T[BH*LL*LP + 16];
__device__ __align__(16) float g_P[BH*LL*LP + 16];
__device__ __align__(16) float g_U[BH*LL*LP + 16];
__device__ __align__(16) float g_O0[NROW*DD];
__device__ __align__(16) float g_O1[NROW*DD];
__device__ float g_deg[BH*LP];

// ---------------- helpers -----------------------------------------------------
__device__ __forceinline__ float4 ld4(const float* p) { return *(const float4*)p; }
__device__ __forceinline__ float4 f4z() { return make_float4(0.f, 0.f, 0.f, 0.f); }

__device__ __forceinline__ unsigned long long pk2(float lo, float hi) {
    unsigned long long r;
    asm("mov.b64 %0,{%1,%2};" : "=l"(r) : "f"(lo), "f"(hi));
    return r;
}
__device__ __forceinline__ void fma2(unsigned long long& d,
                                     unsigned long long a, unsigned long long b) {
    asm("fma.rn.f32x2 %0,%1,%2,%0;" : "+l"(d) : "l"(a), "l"(b));
}
__device__ __forceinline__ float2 up2(unsigned long long v) {
    float2 f;
    asm("mov.b64 {%0,%1},%2;" : "=f"(f.x), "=f"(f.y) : "l"(v));
    return f;
}

// C[4][4] += A(.. x16, stride AST) * B(16 x .., stride BST), packed f32x2
template<int AST, int BST>
__device__ __forceinline__ void inner16(const float* As, const float* Bs,
                                        int ty4, int tx4, unsigned long long acc[4][2]) {
#pragma unroll
    for (int kk = 0; kk < 16; kk++) {
        float4 bv = *(const float4*)(Bs + kk*BST + tx4);
        unsigned long long b01 = pk2(bv.x, bv.y);
        unsigned long long b23 = pk2(bv.z, bv.w);
#pragma unroll
        for (int r = 0; r < 4; r++) {
            float ar = As[(ty4 + r)*AST + kk];
            unsigned long long aa = pk2(ar, ar);
            fma2(acc[r][0], aa, b01);
            fma2(acc[r][1], aa, b23);
        }
    }
}

// C[2][4] variant
template<int AST, int BST>
__device__ __forceinline__ void inner16_2(const float* As, const float* Bs,
                                          int ty2, int tx4, unsigned long long acc[2][2]) {
#pragma unroll
    for (int kk = 0; kk < 16; kk++) {
        float4 bv = *(const float4*)(Bs + kk*BST + tx4);
        unsigned long long b01 = pk2(bv.x, bv.y);
        unsigned long long b23 = pk2(bv.z, bv.w);
#pragma unroll
        for (int r = 0; r < 2; r++) {
            float ar = As[(ty2 + r)*AST + kk];
            unsigned long long aa = pk2(ar, ar);
            fma2(acc[r][0], aa, b01);
            fma2(acc[r][1], aa, b23);
        }
    }
}

// ---------------- K1: qkv projections ------------------------------------------
// grid (12, 15), block (16, 8)
__global__ void qkv_kernel(const float* __restrict__ x,
                           const float* __restrict__ Wq,
                           const float* __restrict__ Wk,
                           const float* __restrict__ Wv) {
    __shared__ __align__(16) float Xs[32][20];
    __shared__ __align__(16) float Ws[16][68];
    int tx = threadIdx.x, ty = threadIdx.y;
    int tid = ty*16 + tx;
    int m0 = blockIdx.y * 32;
    int c0 = blockIdx.x * 64;
    const float* W = (c0 < 256) ? Wq : (c0 < 512) ? Wk : Wv;
    int cw0 = c0 & 255;
    unsigned long long acc[4][2] = {};
    for (int k0 = 0; k0 < 256; k0 += 16) {
        { int ii = tid >> 2, f = tid & 3;
          int m = m0 + ii;
          float4 v = (m < NROW) ? ld4(x + m*256 + k0 + 4*f) : f4z();
          *(float4*)&Xs[ii][4*f] = v; }
#pragma unroll
        for (int s = 0; s < 2; s++) {
            int idx = tid + 128*s;
            int ll = idx >> 2, g = idx & 3;
            float4 w = ld4(W + (cw0 + ll)*256 + k0 + 4*g);
            Ws[4*g+0][ll] = w.x; Ws[4*g+1][ll] = w.y;
            Ws[4*g+2][ll] = w.z; Ws[4*g+3][ll] = w.w;
        }
        __syncthreads();
        inner16<20, 68>(&Xs[0][0], &Ws[0][0], ty*4, tx*4, acc);
        __syncthreads();
    }
    int which = c0 >> 8, hb = (c0 & 255) >> 6;
    float* dst = (which == 0) ? g_q : (which == 1) ? g_k : g_v;
#pragma unroll
    for (int r = 0; r < 4; r++) {
        int m = m0 + ty*4 + r;
        if (m < NROW) {
            int b = (m >= LL) ? 1 : 0;
            int l = m - b*LL;
            float2 lo = up2(acc[r][0]), hi = up2(acc[r][1]);
            *(float4*)(dst + ((b*HH + hb)*LL + l)*HD + tx*4) =
                make_float4(lo.x, lo.y, hi.x, hi.y);
        }
    }
}

// ---------------- K2: S = q k^T, zero g_deg -------------------------------------
// grid (4, 4, 8), block (16,16)
__global__ void s_kernel() {
    __shared__ __align__(16) float Qs[64][20];
    __shared__ __align__(16) float Ks[16][68];
    int tx = threadIdx.x, ty = threadIdx.y;
    int tid = ty*16 + tx;
    int bh = blockIdx.z;
    if (blockIdx.x == 0 && blockIdx.y == 0 && tid < LP) g_deg[bh*LP + tid] = 0.f;
    int i0 = blockIdx.y*64, j0 = blockIdx.x*64;
    const float* qb = g_q + bh*LL*HD;
    const float* kb = g_k + bh*LL*HD;
    unsigned long long acc[4][2] = {};
#pragma unroll
    for (int d0 = 0; d0 < 64; d0 += 16) {
        { int ii = tid >> 2, f = tid & 3;
          int i = i0 + ii;
          float4 v = (i < LL) ? ld4(qb + i*HD + d0 + 4*f) : f4z();
          *(float4*)&Qs[ii][4*f] = v; }
        { int ll = tid >> 2, f = tid & 3;
          int j = j0 + ll;
          float4 v = (j < LL) ? ld4(kb + j*HD + d0 + 4*f) : f4z();
          Ks[4*f+0][ll] = v.x; Ks[4*f+1][ll] = v.y;
          Ks[4*f+2][ll] = v.z; Ks[4*f+3][ll] = v.w; }
        __syncthreads();
        inner16<20, 68>(&Qs[0][0], &Ks[0][0], ty*4, tx*4, acc);
        __syncthreads();
    }
    float* Sb = g_S + (size_t)bh*LL*LP;
    int jc = j0 + tx*4;
    if (jc < LP) {
#pragma unroll
        for (int r = 0; r < 4; r++) {
            int i = i0 + ty*4 + r;
            if (i < LL) {
                float2 lo = up2(acc[r][0]), hi = up2(acc[r][1]);
                *(float4*)(Sb + i*LP + jc) = make_float4(lo.x, lo.y, hi.x, hi.y);
            }
        }
    }
}

// ---------------- K3: adjacency, 64x64 symmetric tile pairs, j-split x5 ---------
// grid (10, 8, 5), block (16,16). Partial over j in [js*48, js*48+48).
__global__ void __launch_bounds__(256, 3) a_kernel() {
    __shared__ __align__(16) float Si[2][16][68];
    __shared__ __align__(16) float Sk[2][16][68];
    __shared__ float scol[64];
    int tx = threadIdx.x, ty = threadIdx.y;
    int tid = ty*16 + tx;
    int p = blockIdx.x, bh = blockIdx.y, js = blockIdx.z;
    int jbase = js * 48;
    const int NC = 3;
    int ti = 0, rem = p;
    while (rem >= 4 - ti) { rem -= 4 - ti; ti++; }
    int tk = ti + rem;
    int i0 = ti*64, k0 = tk*64;
    const float* Sb = g_S + (size_t)bh*LL*LP;
    const float THR = 6.4f;   // == 0.1f*64 exactly
    if (tid < 64) scol[tid] = 0.f;

    bool isI = tid < 128;
    int lr = (tid & 127) >> 1;        // 0..63
    int lf = (tid & 1) * 8;           // 0 or 8
    int lrow = (isI ? i0 : k0) + lr;
    float4 r0, r1;

    auto loadc = [&](int c) {
        int jb = jbase + c*16 + lf;
        if (lrow < LL) {
            r0 = ld4(Sb + lrow*LP + jb);
            r1 = ld4(Sb + lrow*LP + jb + 4);
        } else { r0 = f4z(); r1 = f4z(); }
    };
    auto storec = [&](int st) {
        float (*Ds)[68] = isI ? Si[st] : Sk[st];
        Ds[lf+0][lr] = r0.x; Ds[lf+1][lr] = r0.y;
        Ds[lf+2][lr] = r0.z; Ds[lf+3][lr] = r0.w;
        Ds[lf+4][lr] = r1.x; Ds[lf+5][lr] = r1.y;
        Ds[lf+6][lr] = r1.z; Ds[lf+7][lr] = r1.w;
    };

    float a[4][4] = {};
    loadc(0); storec(0); __syncthreads();
    for (int c = 0; c < NC; c++) {
        int st = c & 1;
        if (c + 1 < NC) loadc(c + 1);
#pragma unroll
        for (int kk = 0; kk < 16; kk++) {
            float4 a4 = *(const float4*)&Si[st][kk][ty*4];
            float4 b4 = *(const float4*)&Sk[st][kk][tx*4];
            float t;
            t = a4.x*b4.x; if (t > THR) a[0][0] += t;
            t = a4.x*b4.y; if (t > THR) a[0][1] += t;
            t = a4.x*b4.z; if (t > THR) a[0][2] += t;
            t = a4.x*b4.w; if (t > THR) a[0][3] += t;
            t = a4.y*b4.x; if (t > THR) a[1][0] += t;
            t = a4.y*b4.y; if (t > THR) a[1][1] += t;
            t = a4.y*b4.z; if (t > THR) a[1][2] += t;
            t = a4.y*b4.w; if (t > THR) a[1][3] += t;
            t = a4.z*b4.x; if (t > THR) a[2][0] += t;
            t = a4.z*b4.y; if (t > THR) a[2][1] += t;
            t = a4.z*b4.z; if (t > THR) a[2][2] += t;
            t = a4.z*b4.w; if (t > THR) a[2][3] += t;
            t = a4.w*b4.x; if (t > THR) a[3][0] += t;
            t = a4.w*b4.y; if (t > THR) a[3][1] += t;
            t = a4.w*b4.z; if (t > THR) a[3][2] += t;
            t = a4.w*b4.w; if (t > THR) a[3][3] += t;
        }
        if (c + 1 < NC) storec(st ^ 1);
        __syncthreads();
    }

    const float sc = 1.f / (64.f * 225.f);
    int ig0 = i0 + ty*4, kg0 = k0 + tx*4;
    float av[4][4];
#pragma unroll
    for (int r = 0; r < 4; r++)
#pragma unroll
        for (int c = 0; c < 4; c++) {
            float v = a[r][c] * sc;
            av[r][c] = (ig0 + r == kg0 + c) ? 0.f : v;
        }
    float* Ab = ((js == 0) ? g_A0 : (js == 1) ? g_A1 : (js == 2) ? g_A2 :
                 (js == 3) ? g_A3 : g_A4) + (size_t)bh*LL*LP;
    if (kg0 < LP) {
#pragma unroll
        for (int r = 0; r < 4; r++) {
            int ig = ig0 + r;
            if (ig < LL)
                *(float4*)(Ab + ig*LP + kg0) =
                    make_float4(av[r][0], av[r][1], av[r][2], av[r][3]);
        }
    }
    if (ti != tk) {   // mirror; ig0 <= 188 < LP always
#pragma unroll
        for (int c = 0; c < 4; c++) {
            int kg = kg0 + c;
            if (kg < LL)
                *(float4*)(Ab + kg*LP + ig0) =
                    make_float4(av[0][c], av[1][c], av[2][c], av[3][c]);
        }
    }
#pragma unroll
    for (int r = 0; r < 4; r++) {
        float rs = (av[r][0] + av[r][1]) + (av[r][2] + av[r][3]);
#pragma unroll
        for (int off = 8; off > 0; off >>= 1)
            rs += __shfl_xor_sync(0xffffffffu, rs, off);
        int ig = ig0 + r;
        if (tx == 0 && ig < LL) atomicAdd(&g_deg[bh*LP + ig], rs);
    }
    if (ti != tk) {
#pragma unroll
        for (int c = 0; c < 4; c++) {
            float cs = (av[0][c] + av[1][c]) + (av[2][c] + av[3][c]);
            atomicAdd(&scol[tx*4 + c], cs);
        }
        __syncthreads();
        if (tid < 64) {
            int kg = k0 + tid;
            if (kg < LL) atomicAdd(&g_deg[bh*LP + kg], scol[tid]);
        }
    }
}

// ---------------- K4: Ah = (A0+..+A4 + I) * dis_i * dis_k / sqrt(8) -------------
// grid (57, 8), block 256. 4 rows per block (one item per thread).
__global__ void ahat_kernel() {
    __shared__ float sdis[LP];
    int tid = threadIdx.x;
    int rg = blockIdx.x, bh = blockIdx.y;
    if (tid < LP) sdis[tid] = rsqrtf(fmaxf(1.f + g_deg[bh*LP + tid], 1e-6f));
    __syncthreads();
    const float SC = 0.35355339059327373f;  // 1/sqrt(8)
    size_t off = (size_t)bh*LL*LP;
    const float* A0 = g_A0 + off;
    const float* A1 = g_A1 + off;
    const float* A2 = g_A2 + off;
    const float* A3 = g_A3 + off;
    const float* A4 = g_A4 + off;
    float* Ah = g_Ah + off;
    if (tid < 4*60) {
        int r = tid / 60, c4 = (tid % 60) * 4;
        int i = rg*4 + r;
        if (i < LL) {
            float4 a0 = ld4(A0 + i*LP + c4);
            float4 a1 = ld4(A1 + i*LP + c4);
            float4 a2 = ld4(A2 + i*LP + c4);
            float4 a3 = ld4(A3 + i*LP + c4);
            float4 a4 = ld4(A4 + i*LP + c4);
            float di = sdis[i] * SC;
            float4 dk = *(const float4*)&sdis[c4];
            float4 o;
            o.x = (a0.x + a1.x + a2.x + a3.x + a4.x + ((i == c4 + 0) ? 1.f : 0.f)) * di * dk.x;
            o.y = (a0.y + a1.y + a2.y + a3.y + a4.y + ((i == c4 + 1) ? 1.f : 0.f)) * di * dk.y;
            o.z = (a0.z + a1.z + a2.z + a3.z + a4.z + ((i == c4 + 2) ? 1.f : 0.f)) * di * dk.z;
            o.w = (a0.w + a1.w + a2.w + a3.w + a4.w + ((i == c4 + 3) ? 1.f : 0.f)) * di * dk.w;
            *(float4*)(Ah + i*LP + c4) = o;
        }
    }
}

// ---------------- K5/K6: pure 225^3 GEMM, 64x64 tile, 4x4/thread, k-split x3 ----
// MODE 0: partials of Ah @ S -> T/P/U    MODE 1: partials of (T+P+U) @ Ah -> A0/A1/A2
// grid (4 j, 4 i, 24 = bh*3+ks), block (16,16)
template<int MODE>
__global__ void __launch_bounds__(256, 3) gemm_kernel() {
    __shared__ __align__(16) float As[2][16][68];   // transposed: As[kk][row]
    __shared__ __align__(16) float Bs[2][16][68];   // Bs[kk][col]
    int tx = threadIdx.x, ty = threadIdx.y;
    int tid = ty*16 + tx;
    int bh = blockIdx.z / 3, ks = blockIdx.z % 3;
    int kbase = ks * 80;
    const int NC = 5;
    int i0 = blockIdx.y*64, j0 = blockIdx.x*64;
    size_t off = (size_t)bh*LL*LP;
    const float* A1p = ((MODE == 0) ? g_Ah : g_T) + off;
    const float* A2p = g_P + off;   // used only in MODE 1
    const float* A3p = g_U + off;   // used only in MODE 1
    const float* B   = ((MODE == 0) ? g_S : g_Ah) + off;
    float* C = (MODE == 0)
        ? (((ks == 0) ? g_T : (ks == 1) ? g_P : g_U) + off)
        : (((ks == 0) ? g_A0 : (ks == 1) ? g_A1 : g_A2) + off);

    int alr = tid >> 2;               // 0..63 (A row)
    int alf = (tid & 3) * 4;          // k sub-offset
    int arow = i0 + alr;
    int bkk = tid >> 4, bj4 = (tid & 15) * 4;
    int bj = j0 + bj4;
    float4 aReg = f4z(), bReg = f4z();

    auto loadc = [&](int c) {
        int kabs = kbase + c*16;
        if (arow < LL) {
            aReg = ld4(A1p + arow*LP + kabs + alf);
            if (MODE == 1) {
                float4 w = ld4(A2p + arow*LP + kabs + alf);
                float4 u = ld4(A3p + arow*LP + kabs + alf);
                aReg.x += w.x + u.x; aReg.y += w.y + u.y;
                aReg.z += w.z + u.z; aReg.w += w.w + u.w;
            }
        } else aReg = f4z();
        int k = kabs + bkk;
        bReg = (k < LL && bj < LP) ? ld4(B + k*LP + bj) : f4z();
    };
    auto storec = [&](int st) {
        As[st][alf+0][alr] = aReg.x; As[st][alf+1][alr] = aReg.y;
        As[st][alf+2][alr] = aReg.z; As[st][alf+3][alr] = aReg.w;
        *(float4*)&Bs[st][bkk][bj4] = bReg;
    };

    unsigned long long acc[4][2] = {};
    loadc(0); storec(0); __syncthreads();
    for (int c = 0; c < NC; c++) {
        int st = c & 1;
        if (c + 1 < NC) loadc(c + 1);
#pragma unroll
        for (int kk = 0; kk < 16; kk++) {
            float4 a4 = *(const float4*)&As[st][kk][ty*4];
            float4 b4 = *(const float4*)&Bs[st][kk][tx*4];
            unsigned long long b01 = pk2(b4.x, b4.y);
            unsigned long long b23 = pk2(b4.z, b4.w);
            unsigned long long aa;
            aa = pk2(a4.x, a4.x); fma2(acc[0][0], aa, b01); fma2(acc[0][1], aa, b23);
            aa = pk2(a4.y, a4.y); fma2(acc[1][0], aa, b01); fma2(acc[1][1], aa, b23);
            aa = pk2(a4.z, a4.z); fma2(acc[2][0], aa, b01); fma2(acc[2][1], aa, b23);
            aa = pk2(a4.w, a4.w); fma2(acc[3][0], aa, b01); fma2(acc[3][1], aa, b23);
        }
        if (c + 1 < NC) storec(st ^ 1);
        __syncthreads();
    }

    int jc = j0 + tx*4;
    if (jc < LP) {
#pragma unroll
        for (int r = 0; r < 4; r++) {
            int i = i0 + ty*4 + r;
            if (i < LL) {
                float2 lo = up2(acc[r][0]), hi = up2(acc[r][1]);
                *(float4*)(C + i*LP + jc) = make_float4(lo.x, lo.y, hi.x, hi.y);
            }
        }
    }
}

// ---------------- K7: fused softmax + O = attn @ v, k-split x2 ------------------
// grid (15, 8, 2), block (16,16). P = A0+A1+A2 partials; O partial per ks.
__global__ void av_kernel() {
    __shared__ __align__(16) float2 PsD[16][18];
    __shared__ __align__(16) float  Vs[16][68];
    __shared__ float smx[16], sinv[16];
    int tx = threadIdx.x, ty = threadIdx.y;
    int tid = ty*16 + tx;
    int bh = blockIdx.y;
    int i0 = blockIdx.x*16;
    int ks = blockIdx.z;
    int klo = ks ? 128 : 0;
    int khi = ks ? LP : 128;
    const float* P0 = g_A0 + (size_t)bh*LL*LP;
    const float* P1 = g_A1 + (size_t)bh*LL*LP;
    const float* P2 = g_A2 + (size_t)bh*LL*LP;
    const float* Vb = g_v + bh*LL*HD;
    {
        int w = tid >> 5, lane = tid & 31;
#pragma unroll
        for (int rr = 0; rr < 2; rr++) {
            int row = w*2 + rr;
            int i = i0 + row;
            if (i < LL) {
                const float* Pr0 = P0 + i*LP;
                const float* Pr1 = P1 + i*LP;
                const float* Pr2 = P2 + i*LP;
                float vb[8];
                float m = -1e30f;
#pragma unroll
                for (int e = 0; e < 8; e++) {
                    int j = lane + 32*e;
                    float v = (j < LL) ? (Pr0[j] + Pr1[j] + Pr2[j]) : -1e30f;
                    vb[e] = v;
                    m = fmaxf(m, v);
                }
#pragma unroll
                for (int off = 16; off > 0; off >>= 1)
                    m = fmaxf(m, __shfl_xor_sync(0xffffffffu, m, off));
                float s = 0.f;
#pragma unroll
                for (int e = 0; e < 8; e++) s += __expf(vb[e] - m);
#pragma unroll
                for (int off = 16; off > 0; off >>= 1)
                    s += __shfl_xor_sync(0xffffffffu, s, off);
                if (lane == 0) { smx[row] = m; sinv[row] = 1.f / s; }
            }
        }
    }
    __syncthreads();
    unsigned long long acc[2] = {};
    for (int k0 = klo; k0 < khi; k0 += 16) {
        if (tid < 64) {
            int row = tid >> 2, f = (tid & 3)*4;
            int i = i0 + row;
            float4 v;
            if (i < LL) {
                float4 v0 = ld4(P0 + i*LP + k0 + f);
                float4 v1 = ld4(P1 + i*LP + k0 + f);
                float4 v2 = ld4(P2 + i*LP + k0 + f);
                float m = smx[row], inv = sinv[row];
                int kb = k0 + f;
                v.x = (kb + 0 < LL) ? __expf(v0.x + v1.x + v2.x - m)*inv : 0.f;
                v.y = (kb + 1 < LL) ? __expf(v0.y + v1.y + v2.y - m)*inv : 0.f;
                v.z = (kb + 2 < LL) ? __expf(v0.z + v1.z + v2.z - m)*inv : 0.f;
                v.w = (kb + 3 < LL) ? __expf(v0.w + v1.w + v2.w - m)*inv : 0.f;
            } else v = f4z();
            PsD[f+0][row] = make_float2(v.x, v.x);
            PsD[f+1][row] = make_float2(v.y, v.y);
            PsD[f+2][row] = make_float2(v.z, v.z);
            PsD[f+3][row] = make_float2(v.w, v.w);
        }
        { int kk = tid >> 4, d4 = (tid & 15)*4;
          int k = k0 + kk;
          float4 v = (k < LL) ? ld4(Vb + k*HD + d4) : f4z();
          *(float4*)&Vs[kk][d4] = v; }
        __syncthreads();
#pragma unroll
        for (int kk = 0; kk < 16; kk++) {
            unsigned long long a = *(const unsigned long long*)&PsD[kk][ty];
            ulonglong2 b = *(const ulonglong2*)&Vs[kk][tx*4];
            fma2(acc[0], a, b.x);
            fma2(acc[1], a, b.y);
        }
        __syncthreads();
    }
    int b = bh >> 2, h = bh & 3;
    int i = i0 + ty;
    if (i < LL) {
        float* Ob = ks ? g_O1 : g_O0;
        float2 lo = up2(acc[0]), hi = up2(acc[1]);
        *(float4*)(Ob + (b*LL + i)*DD + h*HD + tx*4) =
            make_float4(lo.x, lo.y, hi.x, hi.y);
    }
}

// ---------------- K8: out = (O0+O1) @ Wo^T ---------------------------------------
// grid (4, 15), block (16,16)
__global__ void out_kernel(const float* __restrict__ Wo, float* __restrict__ out) {
    __shared__ __align__(16) float Os[32][20];
    __shared__ __align__(16) float Ws[16][68];
    int tx = threadIdx.x, ty = threadIdx.y;
    int tid = ty*16 + tx;
    int m0 = blockIdx.y*32, c0 = blockIdx.x*64;
    unsigned long long acc[2][2] = {};
    for (int k0 = 0; k0 < 256; k0 += 16) {
        if (tid < 128) {
            int ii = tid >> 2, f = tid & 3;
            int m = m0 + ii;
            float4 v = f4z();
            if (m < NROW) {
                float4 v0 = ld4(g_O0 + m*256 + k0 + 4*f);
                float4 v1 = ld4(g_O1 + m*256 + k0 + 4*f);
                v = make_float4(v0.x + v1.x, v0.y + v1.y, v0.z + v1.z, v0.w + v1.w);
            }
            *(float4*)&Os[ii][4*f] = v;
        } else {
#pragma unroll
            for (int s2 = 0; s2 < 2; s2++) {
                int idx = (tid - 128) + 128*s2;
                int ll = idx >> 2, f = idx & 3;
                float4 w = ld4(Wo + (c0 + ll)*256 + k0 + 4*f);
                Ws[4*f+0][ll] = w.x; Ws[4*f+1][ll] = w.y;
                Ws[4*f+2][ll] = w.z; Ws[4*f+3][ll] = w.w;
            }
        }
        __syncthreads();
        inner16_2<20, 68>(&Os[0][0], &Ws[0][0], ty*2, tx*4, acc);
        __syncthreads();
    }
#pragma unroll
    for (int r = 0; r < 2; r++) {
        int m = m0 + ty*2 + r;
        if (m < NROW) {
            float2 lo = up2(acc[r][0]), hi = up2(acc[r][1]);
            *(float4*)(out + m*256 + c0 + tx*4) =
                make_float4(lo.x, lo.y, hi.x, hi.y);
        }
    }
}

// ---------------- launcher --------------------------------------------------------
extern "C" void kernel_launch(void* const* d_in, const int* in_sizes, int n_in,
                              void* d_out, int out_size) {
    const float* x  = (const float*)d_in[0];
    const float* Wq = (const float*)d_in[1];
    const float* Wk = (const float*)d_in[2];
    const float* Wv = (const float*)d_in[3];
    const float* Wo = (const float*)d_in[4];
    float* out = (float*)d_out;

    dim3 b16(16, 16), b168(16, 8);

    qkv_kernel<<<dim3(12, 15), b168>>>(x, Wq, Wk, Wv);
    s_kernel<<<dim3(4, 4, 8), b16>>>();
    a_kernel<<<dim3(10, 8, 5), b16>>>();
    ahat_kernel<<<dim3(57, 8), 256>>>();
    gemm_kernel<0><<<dim3(4, 4, 24), b16>>>();   // T/P/U partials of Ah@S
    gemm_kernel<1><<<dim3(4, 4, 24), b16>>>();   // A0/A1/A2 partials of (T+P+U)@Ah
    av_kernel<<<dim3(15, 8, 2), b16>>>();        // softmax(A0+A1+A2) @ v -> O0/O1
    out_kernel<<<dim3(4, 15), b16>>>(Wo, out);
}